// round 12
// baseline (speedup 1.0000x reference)
#include <cuda_runtime.h>
#include <math.h>

// Problem shape constants
#define BB   8
#define HHH  1024
#define WWW  1024
#define TW   128     // tile width  (output pixels)
#define TH   16      // tile height (output pixels)
#define NTHREADS 256
#define NBLOCKS  (BB * (HHH / TH) * (WWW / TW))   // 4096

// Accumulator layout (doubles):
//  [0]        focal sum  (Σ over all 3 slices, all pixels, of -log(pt+eps))
//  [1]        edge  sum  (Σ of -log(pt+eps) * |t - ave|)
//  [2  + s*8 + b]  Σ p1          per slice s, batch b
//  [26 + s*8 + b]  Σ p1 * t      per slice s, batch b
//  [50 + b]        Σ t           per batch b
// Zero-initialized at module load; the last block re-zeroes after finalizing,
// so every graph replay starts from a clean state.
__device__ double g_acc[58];
__device__ unsigned int g_count = 0;

__global__ __launch_bounds__(NTHREADS)
void main_kernel(const float* __restrict__ pred,
                 const float* __restrict__ diss,
                 const int*   __restrict__ target,
                 const float* __restrict__ diff,
                 const float* __restrict__ sigma,
                 float*       __restrict__ out)
{
    // target tile (as float) with halo 3: rows [h0-3, h0+TH+3), cols [w0-3, w0+TW+3)
    __shared__ float raw[22][136];   // 22 rows x 134 used cols (pad to 136)
    __shared__ float rs5[20][128];   // 5-wide horizontal sums, rows raw[1..20]
    __shared__ float red[9][8];
    __shared__ unsigned int s_last;
    __shared__ float s_sink;

    const int b  = blockIdx.z;
    const int w0 = blockIdx.x * TW;
    const int h0 = blockIdx.y * TH;
    const int tx = threadIdx.x;          // 0..31
    const int ty = threadIdx.y;          // 0..7
    const int tid = ty * 32 + tx;

    const int* tgt_b = target + (size_t)b * HHH * WWW;

    // ---- load target tile (zero-padded SAME boundary), convert to float once ----
    for (int i = tid; i < 22 * 134; i += NTHREADS) {
        int hh = i / 134, cc = i - hh * 134;
        int gh = h0 - 3 + hh, gw = w0 - 3 + cc;
        float v = 0.f;
        if (gh >= 0 && gh < HHH && gw >= 0 && gw < WWW)
            v = (float)tgt_b[(size_t)gh * WWW + gw];
        raw[hh][cc] = v;
    }
    __syncthreads();

    // ---- stage 1: horizontal 5-sums (lane-linear -> conflict-free) ----
    for (int i = tid; i < 20 * 128; i += NTHREADS) {
        int r = i >> 7, w = i & 127;
        rs5[r][w] = raw[r+1][w+1] + raw[r+1][w+2] + raw[r+1][w+3]
                  + raw[r+1][w+4] + raw[r+1][w+5];
    }
    __syncthreads();

    float facc = 0.f, eacc = 0.f;
    float p1s0 = 0.f, p1s1 = 0.f, p1s2 = 0.f;
    float p1t0 = 0.f, p1t1 = 0.f, p1t2 = 0.f;
    float tcf  = 0.f;

    const size_t hw = (size_t)HHH * WWW;
    const float* pl_a0 = pred + ((size_t)b        * 2 + 0) * hw;
    const float* pl_a1 = pred + ((size_t)b        * 2 + 1) * hw;
    const float* pl_q0 = pred + ((size_t)(8 + b)  * 2 + 0) * hw;
    const float* pl_q1 = pred + ((size_t)(8 + b)  * 2 + 1) * hw;
    const float* pl_c0 = diss + ((size_t)b        * 2 + 0) * hw;
    const float* pl_c1 = diss + ((size_t)b        * 2 + 1) * hw;

    #pragma unroll
    for (int rr = 0; rr < 2; rr++) {
        const int oh = ty * 2 + rr;            // 0..15 within tile
        const size_t base = (size_t)(h0 + oh) * WWW + w0 + tx;
        const int hr = oh + 3;

        // Front-batch all 24 scalar loads (coalesced 128B/warp-instr, high MLP)
        float a0[4], a1[4], q0[4], q1[4], c0[4], c1[4];
        #pragma unroll
        for (int j = 0; j < 4; j++) {
            size_t p = base + 32 * j;
            a0[j] = __ldcs(pl_a0 + p);  a1[j] = __ldcs(pl_a1 + p);
            q0[j] = __ldcs(pl_q0 + p);  q1[j] = __ldcs(pl_q1 + p);
            c0[j] = __ldcs(pl_c0 + p);  c1[j] = __ldcs(pl_c1 + p);
        }

        #pragma unroll
        for (int j = 0; j < 4; j++) {
            const int c  = tx + 32 * j;    // output col within tile (lane-consecutive)
            const int wr = c + 3;          // raw col of center

            const float tf = raw[hr][wr];
            // 29-cell circular mask = 5x5 box + (±3,0) + (0,±3)
            float s29 = rs5[oh  ][c] + rs5[oh+1][c] + rs5[oh+2][c]
                      + rs5[oh+3][c] + rs5[oh+4][c]
                      + raw[hr][c] + raw[hr][c+6]    // (0,-3),(0,+3)
                      + raw[oh][wr] + raw[oh+6][wr]; // (-3,0),(+3,0)

            const float at = fabsf(tf - s29 * (1.0f / 29.0f));
            const bool  t1 = tf > 0.5f;

            // slice 0 : softmax over 2 channels.
            // p1 = 1/(1+e^d), p0 = e^d/(1+e^d); since |d| <~ 9, p >> eps, so
            // -log(pt+eps) == t ? L : L-d with L = log(1+e^d) (to ~2e-6 abs).
            {
                float d  = a0[j] - a1[j];
                float e  = __expf(d);
                float z  = 1.0f + e;
                float L  = __logf(z);
                float p1 = __fdividef(1.0f, z);
                float nl = t1 ? L : (L - d);
                facc += nl; eacc += nl * at;
                p1s0 += p1; p1t0 += t1 ? p1 : 0.0f;
            }
            // slice 1 : softmax over 2 channels
            {
                float d  = q0[j] - q1[j];
                float e  = __expf(d);
                float z  = 1.0f + e;
                float L  = __logf(z);
                float p1 = __fdividef(1.0f, z);
                float nl = t1 ? L : (L - d);
                facc += nl; eacc += nl * at;
                p1s1 += p1; p1t1 += t1 ? p1 : 0.0f;
            }
            // slice 2 : raw Diss probabilities (can be ~0 -> keep eps)
            {
                float p0 = c0[j];
                float p1 = c1[j];
                float pt = t1 ? p1 : p0;
                float nl = -__logf(pt + 1e-10f);
                facc += nl; eacc += nl * at;
                p1s2 += p1; p1t2 += t1 ? p1 : 0.0f;
            }
            tcf += tf;
        }
    }

    // ---- block reduction: warp shuffles, then 8 warp partials per value ----
    float vals[9] = {facc, eacc, p1s0, p1s1, p1s2, p1t0, p1t1, p1t2, tcf};
    #pragma unroll
    for (int k = 0; k < 9; k++) {
        float v = vals[k];
        #pragma unroll
        for (int o = 16; o; o >>= 1) v += __shfl_xor_sync(0xFFFFFFFFu, v, o);
        if ((tid & 31) == 0) red[k][tid >> 5] = v;
    }
    __syncthreads();

    // ---- global accumulation WITH completion proof (no gpu-scope fence!).
    // atomicAdd return value == the add has been performed at L2 (the GPU
    // point of coherence; RED/ATOM bypass L1). Consuming the return through
    // a non-foldable FP op + STS forces the wait before BAR.SYNC. This gives
    // the same ordering __threadfence() would, without the CCTL.IVALL L1
    // flush that a gpu-scope fence costs on sm_103a (R8 regression).
    if (tid < 9) {
        float s = 0.f;
        #pragma unroll
        for (int w = 0; w < 8; w++) s += red[tid][w];
        int addr;
        if      (tid == 0) addr = 0;
        else if (tid == 1) addr = 1;
        else if (tid <  5) addr = 2  + (tid - 2) * 8 + b;
        else if (tid <  8) addr = 26 + (tid - 5) * 8 + b;
        else               addr = 50 + b;
        double r = atomicAdd(&g_acc[addr], (double)s);
        // r*0.0 cannot be constant-folded (could be NaN/Inf): real dependence.
        *(volatile float*)&s_sink = (float)(r * 0.0);
    }
    __syncthreads();   // all 9 L2 adds complete before the ticket below

    if (tid == 0) {
        unsigned int ticket = atomicAdd(&g_count, 1u);
        s_last = (ticket == NBLOCKS - 1) ? 1u : 0u;
    }
    __syncthreads();
    if (!s_last || tid >= 32) return;

    // ---- last block: one-warp finalize. All blocks' tickets are in, so all
    // their g_acc adds completed at L2 (proven per-block above). This SM's L1
    // never cached g_acc (writes were L2 atomics); volatile loads keep
    // compiler ordering honest.
    const int lane = tx;
    volatile double* acc = g_acc;

    double term = 0.0;
    if (lane < 24) {
        int s = lane >> 3, bb = lane & 7;
        double I = acc[26 + s * 8 + bb];
        double U = acc[2  + s * 8 + bb] + acc[50 + bb];
        term = 2.0 * I / (U + 1e-10);
    }
    double fsum = acc[0];
    double esum = acc[1];

    #pragma unroll
    for (int o = 16; o; o >>= 1)
        term += __shfl_xor_sync(0xFFFFFFFFu, term, o);
    // dice = Σ_s (1 - mean_b(term)) = 3 - term_total / 8
    double dice = 3.0 - term / 8.0;

    if (lane == 0) {
        float sf0 = sigma[0] * sigma[0];
        float sf1 = sigma[1] * sigma[1];
        float sf2 = sigma[2] * sigma[2];
        double s0 = (double)sf0, s1 = (double)sf1, s2 = (double)sf2;

        const double Np = 8.0 * 1024.0 * 1024.0;   // B*H*W per slice

        double loss = fsum / Np / s0
                    + dice / s1
                    + esum / Np / s2
                    + (double)diff[0]
                    + 0.5 * (log(s0) + log(s1) + log(s2));
        out[0] = (float)loss;
    }

    // ---- re-zero accumulators + ticket for the next graph replay.
    // All g_acc reads above completed in-warp (shuffle reduction synced).
    // Kernel-completion ordering makes these visible to the next replay.
    __syncwarp();
    if (lane < 29) { acc[lane] = 0.0; acc[lane + 29] = 0.0; }
    if (lane == 0) *(volatile unsigned int*)&g_count = 0u;
}

extern "C" void kernel_launch(void* const* d_in, const int* in_sizes, int n_in,
                              void* d_out, int out_size)
{
    const float* pred   = (const float*)d_in[0];  // (2,8,2,1024,1024) f32
    const float* diss   = (const float*)d_in[1];  // (1,8,2,1024,1024) f32
    const int*   target = (const int*)  d_in[2];  // (8,1024,1024) i32
    const float* diff   = (const float*)d_in[3];  // scalar f32
    const float* sigma  = (const float*)d_in[4];  // (3,) f32
    float* out = (float*)d_out;

    dim3 grid(WWW / TW, HHH / TH, BB);   // (8, 64, 8) = 4096 blocks
    dim3 block(32, 8);
    main_kernel<<<grid, block>>>(pred, diss, target, diff, sigma, out);
}

// round 13
// speedup vs baseline: 1.0331x; 1.0331x over previous
#include <cuda_runtime.h>
#include <math.h>

// Problem shape constants
#define BB   8
#define HHH  1024
#define WWW  1024
#define TW   128     // tile width  (output pixels)
#define TH   16      // tile height (output pixels)
#define NTHREADS 256

// Accumulator layout (doubles):
//  [0]        focal sum  (Σ over all 3 slices, all pixels, of -log(pt+eps))
//  [1]        edge  sum  (Σ of -log(pt+eps) * |t - ave|)
//  [2  + s*8 + b]  Σ p1          per slice s, batch b
//  [26 + s*8 + b]  Σ p1 * t      per slice s, batch b
//  [50 + b]        Σ t           per batch b
// Zero-initialized at module load; finalize_kernel re-zeroes after reading,
// so every graph replay starts from a clean state.
__device__ double g_acc[58];

// Fast reciprocal on the FMA pipe (no MUFU): bit-trick seed + 2 Newton steps.
// Max rel err ~6e-6 (one-sided), valid for all normal positive floats.
__device__ __forceinline__ float frcp2(float x) {
    float y = __uint_as_float(0x7EF311C3u - __float_as_uint(x));
    y = y * (2.0f - x * y);
    y = y * (2.0f - x * y);
    return y;
}

__global__ __launch_bounds__(NTHREADS, 6)
void main_kernel(const float* __restrict__ pred,
                 const float* __restrict__ diss,
                 const int*   __restrict__ target)
{
    // target tile (as float) with halo 3: rows [h0-3, h0+TH+3), cols [w0-3, w0+TW+3)
    __shared__ float raw[22][136];   // 22 rows x 134 used cols (pad to 136)
    __shared__ float rs5[20][128];   // 5-wide horizontal sums, rows raw[1..20]
    __shared__ float red[9][8];

    const int b  = blockIdx.z;
    const int w0 = blockIdx.x * TW;
    const int h0 = blockIdx.y * TH;
    const int tx = threadIdx.x;          // 0..31
    const int ty = threadIdx.y;          // 0..7
    const int tid = ty * 32 + tx;

    const int* tgt_b = target + (size_t)b * HHH * WWW;

    // ---- load target tile (zero-padded SAME boundary), convert to float once ----
    for (int i = tid; i < 22 * 134; i += NTHREADS) {
        int hh = i / 134, cc = i - hh * 134;
        int gh = h0 - 3 + hh, gw = w0 - 3 + cc;
        float v = 0.f;
        if (gh >= 0 && gh < HHH && gw >= 0 && gw < WWW)
            v = (float)tgt_b[(size_t)gh * WWW + gw];
        raw[hh][cc] = v;
    }
    __syncthreads();

    // ---- stage 1: horizontal 5-sums (lane-linear -> conflict-free) ----
    for (int i = tid; i < 20 * 128; i += NTHREADS) {
        int r = i >> 7, w = i & 127;
        rs5[r][w] = raw[r+1][w+1] + raw[r+1][w+2] + raw[r+1][w+3]
                  + raw[r+1][w+4] + raw[r+1][w+5];
    }
    __syncthreads();

    float facc = 0.f, eacc = 0.f;
    float p1s0 = 0.f, p1s1 = 0.f, p1s2 = 0.f;
    float p1t0 = 0.f, p1t1 = 0.f, p1t2 = 0.f;
    float tcf  = 0.f;

    const size_t hw = (size_t)HHH * WWW;
    const float* pl_a0 = pred + ((size_t)b        * 2 + 0) * hw;
    const float* pl_a1 = pred + ((size_t)b        * 2 + 1) * hw;
    const float* pl_q0 = pred + ((size_t)(8 + b)  * 2 + 0) * hw;
    const float* pl_q1 = pred + ((size_t)(8 + b)  * 2 + 1) * hw;
    const float* pl_c0 = diss + ((size_t)b        * 2 + 0) * hw;
    const float* pl_c1 = diss + ((size_t)b        * 2 + 1) * hw;

    #pragma unroll
    for (int rr = 0; rr < 2; rr++) {
        const int oh = ty * 2 + rr;            // 0..15 within tile
        const size_t base = (size_t)(h0 + oh) * WWW + w0 + tx;
        const int hr = oh + 3;

        // Front-batch all 24 scalar loads (coalesced 128B/warp-instr, high MLP)
        float a0[4], a1[4], q0[4], q1[4], c0[4], c1[4];
        #pragma unroll
        for (int j = 0; j < 4; j++) {
            size_t p = base + 32 * j;
            a0[j] = __ldcs(pl_a0 + p);  a1[j] = __ldcs(pl_a1 + p);
            q0[j] = __ldcs(pl_q0 + p);  q1[j] = __ldcs(pl_q1 + p);
            c0[j] = __ldcs(pl_c0 + p);  c1[j] = __ldcs(pl_c1 + p);
        }

        #pragma unroll
        for (int j = 0; j < 4; j++) {
            const int c  = tx + 32 * j;    // output col within tile (lane-consecutive)
            const int wr = c + 3;          // raw col of center

            const float tf = raw[hr][wr];
            // 29-cell circular mask = 5x5 box + (±3,0) + (0,±3)
            float s29 = rs5[oh  ][c] + rs5[oh+1][c] + rs5[oh+2][c]
                      + rs5[oh+3][c] + rs5[oh+4][c]
                      + raw[hr][c] + raw[hr][c+6]    // (0,-3),(0,+3)
                      + raw[oh][wr] + raw[oh+6][wr]; // (-3,0),(+3,0)

            const float at = fabsf(tf - s29 * (1.0f / 29.0f));
            const bool  t1 = tf > 0.5f;

            // Merged 3-slice log:
            //   slices 0,1 (softmax): nl_s = log(1+e^{d_s}) - (t?0:d_s),
            //     valid since p >> eps (|d| <~ 9; est. abs err ~2e-6)
            //   slice 2 (raw probs):  nl_2 = -log(pt2 + eps)
            //   nl_total = log(z0*z1/(pt2+eps)) - (t?0:(d0+d1)),  z_s = 1+e^{d_s}
            // One MUFU log replaces three; both rcps on the FMA pipe.
            float d0 = a0[j] - a1[j];
            float d1 = q0[j] - q1[j];
            float e0 = __expf(d0);
            float e1 = __expf(d1);
            float z0 = 1.0f + e0;
            float z1 = 1.0f + e1;
            float zz = z0 * z1;

            float pt2 = (t1 ? c1[j] : c0[j]) + 1e-10f;
            float nl  = __logf(zz * frcp2(pt2));
            nl -= t1 ? 0.0f : (d0 + d1);

            float w   = frcp2(zz);       // 1/(z0*z1)
            float p10 = z1 * w;          // 1/z0
            float p11 = z0 * w;          // 1/z1
            float p12 = c1[j];

            facc += nl;  eacc += nl * at;
            p1s0 += p10; p1s1 += p11; p1s2 += p12;
            p1t0 += t1 ? p10 : 0.0f;
            p1t1 += t1 ? p11 : 0.0f;
            p1t2 += t1 ? p12 : 0.0f;
            tcf  += tf;
        }
    }

    // ---- block reduction: warp shuffles, then 8 warp partials per value ----
    float vals[9] = {facc, eacc, p1s0, p1s1, p1s2, p1t0, p1t1, p1t2, tcf};
    #pragma unroll
    for (int k = 0; k < 9; k++) {
        float v = vals[k];
        #pragma unroll
        for (int o = 16; o; o >>= 1) v += __shfl_xor_sync(0xFFFFFFFFu, v, o);
        if ((tid & 31) == 0) red[k][tid >> 5] = v;
    }
    __syncthreads();

    if (tid < 9) {
        float s = 0.f;
        #pragma unroll
        for (int w = 0; w < 8; w++) s += red[tid][w];
        int addr;
        if      (tid == 0) addr = 0;
        else if (tid == 1) addr = 1;
        else if (tid <  5) addr = 2  + (tid - 2) * 8 + b;
        else if (tid <  8) addr = 26 + (tid - 5) * 8 + b;
        else               addr = 50 + b;
        atomicAdd(&g_acc[addr], (double)s);
    }
}

// One-warp finalize: all g_acc loads issue in parallel (one latency wave),
// dice terms reduced via shuffles. Lane 0 writes the scalar result.
__global__ __launch_bounds__(32)
void finalize_kernel(const float* __restrict__ diff,
                     const float* __restrict__ sigma,
                     float* __restrict__ out)
{
    const int lane = threadIdx.x;

    // Dice term for (s,b) pair on lanes 0..23:
    double term = 0.0;
    if (lane < 24) {
        int s = lane >> 3, bb = lane & 7;
        double I = g_acc[26 + s * 8 + bb];
        double U = g_acc[2  + s * 8 + bb] + g_acc[50 + bb];
        term = 2.0 * I / (U + 1e-10);
    }
    double fsum = g_acc[0];
    double esum = g_acc[1];

    #pragma unroll
    for (int o = 16; o; o >>= 1)
        term += __shfl_xor_sync(0xFFFFFFFFu, term, o);
    // dice = Σ_s (1 - mean_b(term)) = 3 - term_total / 8
    double dice = 3.0 - term / 8.0;

    if (lane == 0) {
        float sf0 = sigma[0] * sigma[0];
        float sf1 = sigma[1] * sigma[1];
        float sf2 = sigma[2] * sigma[2];
        double s0 = (double)sf0, s1 = (double)sf1, s2 = (double)sf2;

        const double Np = 8.0 * 1024.0 * 1024.0;   // B*H*W per slice

        double loss = fsum / Np / s0
                    + dice / s1
                    + esum / Np / s2
                    + (double)diff[0]
                    + 0.5 * (log(s0) + log(s1) + log(s2));
        out[0] = (float)loss;
    }

    // Re-zero accumulators for next replay (all g_acc reads above completed
    // in-warp; shuffle reduction synchronized the warp).
    __syncwarp();
    if (lane < 29) { g_acc[lane] = 0.0; g_acc[lane + 29] = 0.0; }
}

extern "C" void kernel_launch(void* const* d_in, const int* in_sizes, int n_in,
                              void* d_out, int out_size)
{
    const float* pred   = (const float*)d_in[0];  // (2,8,2,1024,1024) f32
    const float* diss   = (const float*)d_in[1];  // (1,8,2,1024,1024) f32
    const int*   target = (const int*)  d_in[2];  // (8,1024,1024) i32
    const float* diff   = (const float*)d_in[3];  // scalar f32
    const float* sigma  = (const float*)d_in[4];  // (3,) f32
    float* out = (float*)d_out;

    dim3 grid(WWW / TW, HHH / TH, BB);   // (8, 64, 8) = 4096 blocks
    dim3 block(32, 8);
    main_kernel<<<grid, block>>>(pred, diss, target);
    finalize_kernel<<<1, 32>>>(diff, sigma, out);
}

// round 14
// speedup vs baseline: 1.1068x; 1.0714x over previous
#include <cuda_runtime.h>
#include <math.h>

// Problem shape constants
#define BB   8
#define HHH  1024
#define WWW  1024
#define TW   128     // tile width  (output pixels)
#define TH   16      // tile height (output pixels)
#define NTHREADS 256

// Accumulator layout (doubles):
//  [0]        focal sum  (Σ over all 3 slices, all pixels, of -log(pt+eps))
//  [1]        edge  sum  (Σ of -log(pt+eps) * |t - ave|)
//  [2  + s*8 + b]  Σ p1          per slice s, batch b
//  [26 + s*8 + b]  Σ p1 * t      per slice s, batch b
//  [50 + b]        Σ t           per batch b
// Zero-initialized at module load; finalize_kernel re-zeroes after reading,
// so every graph replay starts from a clean state.
__device__ double g_acc[58];

// Fast reciprocal on the FMA pipe (no MUFU): bit-trick seed + 2 Newton steps.
// Max rel err ~6e-6 (one-sided), valid for all normal positive floats.
__device__ __forceinline__ float frcp2(float x) {
    float y = __uint_as_float(0x7EF311C3u - __float_as_uint(x));
    y = y * (2.0f - x * y);
    y = y * (2.0f - x * y);
    return y;
}

__global__ __launch_bounds__(NTHREADS, 6)
void main_kernel(const float* __restrict__ pred,
                 const float* __restrict__ diss,
                 const int*   __restrict__ target)
{
    // target tile (as float) with halo 3: rows [h0-3, h0+TH+3), cols [w0-3, w0+TW+3)
    __shared__ float raw[22][136];   // 22 rows x 134 used cols (pad to 136)
    __shared__ float rs5[20][128];   // 5-wide horizontal sums, rows raw[1..20]
    __shared__ float red[9][8];

    const int b  = blockIdx.z;
    const int w0 = blockIdx.x * TW;
    const int h0 = blockIdx.y * TH;
    const int tx = threadIdx.x;          // 0..31
    const int ty = threadIdx.y;          // 0..7
    const int tid = ty * 32 + tx;

    const int* tgt_b = target + (size_t)b * HHH * WWW;

    // ---- load target tile (zero-padded SAME boundary), convert to float once ----
    for (int i = tid; i < 22 * 134; i += NTHREADS) {
        int hh = i / 134, cc = i - hh * 134;
        int gh = h0 - 3 + hh, gw = w0 - 3 + cc;
        float v = 0.f;
        if (gh >= 0 && gh < HHH && gw >= 0 && gw < WWW)
            v = (float)tgt_b[(size_t)gh * WWW + gw];
        raw[hh][cc] = v;
    }
    __syncthreads();

    // ---- stage 1: horizontal 5-sums (lane-linear -> conflict-free) ----
    for (int i = tid; i < 20 * 128; i += NTHREADS) {
        int r = i >> 7, w = i & 127;
        rs5[r][w] = raw[r+1][w+1] + raw[r+1][w+2] + raw[r+1][w+3]
                  + raw[r+1][w+4] + raw[r+1][w+5];
    }
    __syncthreads();

    float facc = 0.f, eacc = 0.f;
    float p1s0 = 0.f, p1s1 = 0.f, p1s2 = 0.f;
    float p1t0 = 0.f, p1t1 = 0.f, p1t2 = 0.f;
    float tcf  = 0.f;
    float s5v[4];   // per-j vertical 5-sum of rs5, reused across the rr rows
                    // (exact: small-integer values are exact in fp32)

    const size_t hw = (size_t)HHH * WWW;
    const float* pl_a0 = pred + ((size_t)b        * 2 + 0) * hw;
    const float* pl_a1 = pred + ((size_t)b        * 2 + 1) * hw;
    const float* pl_q0 = pred + ((size_t)(8 + b)  * 2 + 0) * hw;
    const float* pl_q1 = pred + ((size_t)(8 + b)  * 2 + 1) * hw;
    const float* pl_c0 = diss + ((size_t)b        * 2 + 0) * hw;
    const float* pl_c1 = diss + ((size_t)b        * 2 + 1) * hw;

    #pragma unroll
    for (int rr = 0; rr < 2; rr++) {
        const int oh = ty * 2 + rr;            // 0..15 within tile
        const size_t base = (size_t)(h0 + oh) * WWW + w0 + tx;
        const int hr = oh + 3;

        // Front-batch all 24 scalar loads (coalesced 128B/warp-instr, high MLP)
        float a0[4], a1[4], q0[4], q1[4], c0[4], c1[4];
        #pragma unroll
        for (int j = 0; j < 4; j++) {
            size_t p = base + 32 * j;
            a0[j] = __ldcs(pl_a0 + p);  a1[j] = __ldcs(pl_a1 + p);
            q0[j] = __ldcs(pl_q0 + p);  q1[j] = __ldcs(pl_q1 + p);
            c0[j] = __ldcs(pl_c0 + p);  c1[j] = __ldcs(pl_c1 + p);
        }

        #pragma unroll
        for (int j = 0; j < 4; j++) {
            const int c  = tx + 32 * j;    // output col within tile (lane-consecutive)
            const int wr = c + 3;          // raw col of center

            const float tf = raw[hr][wr];
            // Vertical 5-sum of rs5: full sum on first row, sliding update on
            // the second (window shifts down by 1: +row oh+4, -row oh-1).
            if (rr == 0)
                s5v[j] = rs5[oh  ][c] + rs5[oh+1][c] + rs5[oh+2][c]
                       + rs5[oh+3][c] + rs5[oh+4][c];
            else
                s5v[j] += rs5[oh+4][c] - rs5[oh-1][c];

            // 29-cell circular mask = 5x5 box + (±3,0) + (0,±3)
            float s29 = s5v[j]
                      + raw[hr][c] + raw[hr][c+6]    // (0,-3),(0,+3)
                      + raw[oh][wr] + raw[oh+6][wr]; // (-3,0),(+3,0)

            const float at = fabsf(tf - s29 * (1.0f / 29.0f));
            const bool  t1 = tf > 0.5f;

            // Merged 3-slice log:
            //   slices 0,1 (softmax): nl_s = log(1+e^{d_s}) - (t?0:d_s),
            //     valid since p >> eps (|d| <~ 9; est. abs err ~2e-6)
            //   slice 2 (raw probs):  nl_2 = -log(pt2 + eps)
            //   nl_total = log(z0*z1/(pt2+eps)) - (t?0:(d0+d1)),  z_s = 1+e^{d_s}
            float d0 = a0[j] - a1[j];
            float d1 = q0[j] - q1[j];
            float e0 = __expf(d0);
            float e1 = __expf(d1);
            float z0 = 1.0f + e0;
            float z1 = 1.0f + e1;
            float zz = z0 * z1;

            float pt2 = (t1 ? c1[j] : c0[j]) + 1e-10f;
            float nl  = __logf(zz * frcp2(pt2));
            nl -= t1 ? 0.0f : (d0 + d1);

            float w   = frcp2(zz);       // 1/(z0*z1)
            float p10 = z1 * w;          // 1/z0
            float p11 = z0 * w;          // 1/z1
            float p12 = c1[j];

            facc += nl;  eacc += nl * at;
            p1s0 += p10; p1s1 += p11; p1s2 += p12;
            p1t0 += t1 ? p10 : 0.0f;
            p1t1 += t1 ? p11 : 0.0f;
            p1t2 += t1 ? p12 : 0.0f;
            tcf  += tf;
        }
    }

    // ---- block reduction: warp shuffles, then 8 warp partials per value ----
    float vals[9] = {facc, eacc, p1s0, p1s1, p1s2, p1t0, p1t1, p1t2, tcf};
    #pragma unroll
    for (int k = 0; k < 9; k++) {
        float v = vals[k];
        #pragma unroll
        for (int o = 16; o; o >>= 1) v += __shfl_xor_sync(0xFFFFFFFFu, v, o);
        if ((tid & 31) == 0) red[k][tid >> 5] = v;
    }
    __syncthreads();

    if (tid < 9) {
        float s = 0.f;
        #pragma unroll
        for (int w = 0; w < 8; w++) s += red[tid][w];
        int addr;
        if      (tid == 0) addr = 0;
        else if (tid == 1) addr = 1;
        else if (tid <  5) addr = 2  + (tid - 2) * 8 + b;
        else if (tid <  8) addr = 26 + (tid - 5) * 8 + b;
        else               addr = 50 + b;
        atomicAdd(&g_acc[addr], (double)s);
    }
}

// One-warp finalize, ALL-FP32 math. The previous FP64 version spent ~5us in
// single-thread software DDIV + three double-log subroutines; fp32 MUFU
// log/RCP is ~100x cheaper and the 1e-3 rel-err budget dwarfs fp32 rounding.
__global__ __launch_bounds__(32)
void finalize_kernel(const float* __restrict__ diff,
                     const float* __restrict__ sigma,
                     float* __restrict__ out)
{
    const int lane = threadIdx.x;

    // Dice term for (s,b) pair on lanes 0..23 (loads issue in parallel):
    float term = 0.f;
    if (lane < 24) {
        int s = lane >> 3, bb = lane & 7;
        float I = (float)g_acc[26 + s * 8 + bb];
        float U = (float)g_acc[2  + s * 8 + bb] + (float)g_acc[50 + bb];
        term = 2.0f * I * frcp2(U + 1e-10f);
    }
    float fsum = (float)g_acc[0];
    float esum = (float)g_acc[1];

    #pragma unroll
    for (int o = 16; o; o >>= 1)
        term += __shfl_xor_sync(0xFFFFFFFFu, term, o);
    // dice = Σ_s (1 - mean_b(term)) = 3 - term_total / 8
    float dice = 3.0f - term * 0.125f;

    if (lane == 0) {
        float s0 = sigma[0] * sigma[0];
        float s1 = sigma[1] * sigma[1];
        float s2 = sigma[2] * sigma[2];

        const float invNp = 1.0f / (8.0f * 1024.0f * 1024.0f);

        float loss = fsum * invNp * frcp2(s0)
                   + dice * frcp2(s1)
                   + esum * invNp * frcp2(s2)
                   + diff[0]
                   + 0.5f * (__logf(s0) + __logf(s1) + __logf(s2));
        out[0] = loss;
    }

    // Re-zero accumulators for next replay (all g_acc reads above completed
    // in-warp; shuffle reduction synchronized the warp).
    __syncwarp();
    if (lane < 29) { g_acc[lane] = 0.0; g_acc[lane + 29] = 0.0; }
}

extern "C" void kernel_launch(void* const* d_in, const int* in_sizes, int n_in,
                              void* d_out, int out_size)
{
    const float* pred   = (const float*)d_in[0];  // (2,8,2,1024,1024) f32
    const float* diss   = (const float*)d_in[1];  // (1,8,2,1024,1024) f32
    const int*   target = (const int*)  d_in[2];  // (8,1024,1024) i32
    const float* diff   = (const float*)d_in[3];  // scalar f32
    const float* sigma  = (const float*)d_in[4];  // (3,) f32
    float* out = (float*)d_out;

    dim3 grid(WWW / TW, HHH / TH, BB);   // (8, 64, 8) = 4096 blocks
    dim3 block(32, 8);
    main_kernel<<<grid, block>>>(pred, diss, target);
    finalize_kernel<<<1, 32>>>(diff, sigma, out);
}